// round 5
// baseline (speedup 1.0000x reference)
#include <cuda_runtime.h>

// Shape fixed by setup_inputs: B=8, H=512, W=512, C=16, fp32.
// out[b,y,x,c] = bilinear(image[b], y - flow[...,0], x - flow[...,1]),
// tfa clamping: floor clamped to [0, size-2], then alpha clamped to [0,1].

#define HH 512
#define WW 512
#define CC 16
#define NPIX (8u * HH * WW)   // 2,097,152 pixels

// 4 threads per pixel (one float4 channel chunk each); each thread handles
// TWO pixels (block tile of 128 pixels: p0 in [0,64), p1 = p0 + 64) so that
// 8 independent gather loads are in flight per thread (MLP=8 after the two
// flow loads), instead of 4. Warp lanes stay contiguous within each group.
__global__ __launch_bounds__(256)
void warp_bilinear2_kernel(const float* __restrict__ image,
                           const float* __restrict__ flow,
                           float* __restrict__ out)
{
    const unsigned chunk = threadIdx.x & 3u;          // float4 index within 16 channels
    const unsigned lpix  = threadIdx.x >> 2;          // 0..63 within block
    const unsigned p0 = blockIdx.x * 128u + lpix;     // first pixel
    const unsigned p1 = p0 + 64u;                     // second pixel (same tile)

    // ---- both flow loads issued up front ----
    const float2 f0 = __ldg(reinterpret_cast<const float2*>(flow) + p0);
    const float2 f1 = __ldg(reinterpret_cast<const float2*>(flow) + p1);

    // ---- address math for pixel 0 ----
    unsigned x0 = p0 & (WW - 1u);
    unsigned y0 = (p0 >> 9) & (HH - 1u);
    unsigned b0 = p0 >> 18;
    float qy0 = (float)y0 - f0.x;
    float qx0 = (float)x0 - f0.y;
    float fy0 = fminf(fmaxf(floorf(qy0), 0.0f), (float)(HH - 2));
    float fx0 = fminf(fmaxf(floorf(qx0), 0.0f), (float)(WW - 2));
    float ay0 = fminf(fmaxf(qy0 - fy0, 0.0f), 1.0f);
    float ax0 = fminf(fmaxf(qx0 - fx0, 0.0f), 1.0f);
    int iy0 = (int)fy0, ix0 = (int)fx0;

    // ---- address math for pixel 1 ----
    unsigned x1 = p1 & (WW - 1u);
    unsigned y1 = (p1 >> 9) & (HH - 1u);
    unsigned b1 = p1 >> 18;
    float qy1 = (float)y1 - f1.x;
    float qx1 = (float)x1 - f1.y;
    float fy1 = fminf(fmaxf(floorf(qy1), 0.0f), (float)(HH - 2));
    float fx1 = fminf(fmaxf(floorf(qx1), 0.0f), (float)(WW - 2));
    float ay1 = fminf(fmaxf(qy1 - fy1, 0.0f), 1.0f);
    float ax1 = fminf(fmaxf(qx1 - fx1, 0.0f), 1.0f);
    int iy1 = (int)fy1, ix1 = (int)fx1;

    const float4* __restrict__ img4 = reinterpret_cast<const float4*>(image);
    const size_t dC = CC / 4;                      // next pixel in x (in float4s)
    const size_t dW = (size_t)WW * (CC / 4);       // next row

    size_t base0 = ((size_t)(((b0 * HH + (unsigned)iy0) * WW) + (unsigned)ix0)) * dC + chunk;
    size_t base1 = ((size_t)(((b1 * HH + (unsigned)iy1) * WW) + (unsigned)ix1)) * dC + chunk;

    // ---- all 8 gather loads in flight ----
    float4 tl0 = __ldg(img4 + base0);
    float4 tr0 = __ldg(img4 + base0 + dC);
    float4 bl0 = __ldg(img4 + base0 + dW);
    float4 br0 = __ldg(img4 + base0 + dW + dC);
    float4 tl1 = __ldg(img4 + base1);
    float4 tr1 = __ldg(img4 + base1 + dC);
    float4 bl1 = __ldg(img4 + base1 + dW);
    float4 br1 = __ldg(img4 + base1 + dW + dC);

    float4 top, bot, o0, o1;

    top.x = fmaf(ax0, tr0.x - tl0.x, tl0.x);
    top.y = fmaf(ax0, tr0.y - tl0.y, tl0.y);
    top.z = fmaf(ax0, tr0.z - tl0.z, tl0.z);
    top.w = fmaf(ax0, tr0.w - tl0.w, tl0.w);
    bot.x = fmaf(ax0, br0.x - bl0.x, bl0.x);
    bot.y = fmaf(ax0, br0.y - bl0.y, bl0.y);
    bot.z = fmaf(ax0, br0.z - bl0.z, bl0.z);
    bot.w = fmaf(ax0, br0.w - bl0.w, bl0.w);
    o0.x = fmaf(ay0, bot.x - top.x, top.x);
    o0.y = fmaf(ay0, bot.y - top.y, top.y);
    o0.z = fmaf(ay0, bot.z - top.z, top.z);
    o0.w = fmaf(ay0, bot.w - top.w, top.w);

    top.x = fmaf(ax1, tr1.x - tl1.x, tl1.x);
    top.y = fmaf(ax1, tr1.y - tl1.y, tl1.y);
    top.z = fmaf(ax1, tr1.z - tl1.z, tl1.z);
    top.w = fmaf(ax1, tr1.w - tl1.w, tl1.w);
    bot.x = fmaf(ax1, br1.x - bl1.x, bl1.x);
    bot.y = fmaf(ax1, br1.y - bl1.y, bl1.y);
    bot.z = fmaf(ax1, br1.z - bl1.z, bl1.z);
    bot.w = fmaf(ax1, br1.w - bl1.w, bl1.w);
    o1.x = fmaf(ay1, bot.x - top.x, top.x);
    o1.y = fmaf(ay1, bot.y - top.y, top.y);
    o1.z = fmaf(ay1, bot.z - top.z, top.z);
    o1.w = fmaf(ay1, bot.w - top.w, top.w);

    float4* __restrict__ out4 = reinterpret_cast<float4*>(out);
    out4[(size_t)p0 * dC + chunk] = o0;
    out4[(size_t)p1 * dC + chunk] = o1;
}

extern "C" void kernel_launch(void* const* d_in, const int* in_sizes, int n_in,
                              void* d_out, int out_size)
{
    const float* image = (const float*)d_in[0];
    const float* flow  = (const float*)d_in[1];
    float* out = (float*)d_out;

    // 128 pixels per block -> NPIX/128 = 16384 blocks of 256 threads.
    const unsigned blocks = NPIX / 128u;
    warp_bilinear2_kernel<<<blocks, 256>>>(image, flow, out);
}

// round 13
// speedup vs baseline: 1.0451x; 1.0451x over previous
#include <cuda_runtime.h>

// Shape fixed by setup_inputs: B=8, H=512, W=512, C=16, fp32.
// out[b,y,x,c] = bilinear(image[b], y - flow[...,0], x - flow[...,1]),
// tfa clamping: floor clamped to [0, size-2], then alpha clamped to [0,1].
//
// R6 design: 4 threads/pixel (one float4 chunk each), ITERS=4 pixels per
// thread via a software-pipelined loop: next pixel's flow float2 is
// prefetched BEFORE this pixel's gathers are consumed, so the flow DRAM
// round trip is hidden behind the gather round trip. MLP_p1 stays ~5
// (avoids the front-batch L1tex-queue contention that regressed R5),
// regs stay ~40 (high occupancy). Gather LDGs are data-dependent on their
// iteration's flow load, so ptxas cannot front-batch them across iterations.

#define HH 512
#define WW 512
#define CC 16
#define NPIX (8u * HH * WW)   // 2,097,152 pixels
#define ITERS 4

__global__ __launch_bounds__(256)
void warp_bilinear_pipe_kernel(const float* __restrict__ image,
                               const float* __restrict__ flow,
                               float* __restrict__ out)
{
    const unsigned chunk = threadIdx.x & 3u;                 // float4 index in 16 ch
    unsigned task = blockIdx.x * (256u * ITERS) + threadIdx.x;
    unsigned p = task >> 2;                                  // pixel; +64 per iter

    const float4* __restrict__ img4 = reinterpret_cast<const float4*>(image);
    const float2* __restrict__ flow2 = reinterpret_cast<const float2*>(flow);
    float4* __restrict__ out4 = reinterpret_cast<float4*>(out);

    // Prologue: flow for iteration 0.
    float2 f = __ldg(flow2 + p);

#pragma unroll
    for (int it = 0; it < ITERS; ++it) {
        // Prefetch next pixel's flow before touching this pixel's gathers:
        // its latency hides behind the gather round trip below.
        float2 fn;
        if (it + 1 < ITERS) fn = __ldg(flow2 + (p + 64u));

        const unsigned x = p & (WW - 1u);
        const unsigned y = (p >> 9) & (HH - 1u);
        const unsigned b = p >> 18;

        float qy = (float)y - f.x;
        float qx = (float)x - f.y;
        float fy = fminf(fmaxf(floorf(qy), 0.0f), (float)(HH - 2));
        float fx = fminf(fmaxf(floorf(qx), 0.0f), (float)(WW - 2));
        float ay = fminf(fmaxf(qy - fy, 0.0f), 1.0f);
        float ax = fminf(fmaxf(qx - fx, 0.0f), 1.0f);
        unsigned iy = (unsigned)(int)fy;
        unsigned ix = (unsigned)(int)fx;

        // 32-bit float4 indexing (max index 8.4M, fits easily).
        unsigned base = ((b * HH + iy) * WW + ix) * (CC / 4) + chunk;
        const unsigned dC = CC / 4;            // next pixel in x
        const unsigned dW = WW * (CC / 4);     // next row

        float4 tl = __ldg(img4 + base);
        float4 tr = __ldg(img4 + base + dC);
        float4 bl = __ldg(img4 + base + dW);
        float4 br = __ldg(img4 + base + dW + dC);

        float4 top, bot, o;
        top.x = fmaf(ax, tr.x - tl.x, tl.x);
        top.y = fmaf(ax, tr.y - tl.y, tl.y);
        top.z = fmaf(ax, tr.z - tl.z, tl.z);
        top.w = fmaf(ax, tr.w - tl.w, tl.w);
        bot.x = fmaf(ax, br.x - bl.x, bl.x);
        bot.y = fmaf(ax, br.y - bl.y, bl.y);
        bot.z = fmaf(ax, br.z - bl.z, bl.z);
        bot.w = fmaf(ax, br.w - bl.w, bl.w);
        o.x = fmaf(ay, bot.x - top.x, top.x);
        o.y = fmaf(ay, bot.y - top.y, top.y);
        o.z = fmaf(ay, bot.z - top.z, top.z);
        o.w = fmaf(ay, bot.w - top.w, top.w);

        out4[p * (CC / 4) + chunk] = o;

        f = fn;
        p += 64u;
    }
}

extern "C" void kernel_launch(void* const* d_in, const int* in_sizes, int n_in,
                              void* d_out, int out_size)
{
    const float* image = (const float*)d_in[0];
    const float* flow  = (const float*)d_in[1];
    float* out = (float*)d_out;

    // Total chunk-tasks = NPIX*4 = 8,388,608; each block does 256*ITERS tasks.
    const unsigned blocks = (NPIX * 4u) / (256u * ITERS);   // 8192
    warp_bilinear_pipe_kernel<<<blocks, 256>>>(image, flow, out);
}